// round 2
// baseline (speedup 1.0000x reference)
#include <cuda_runtime.h>
#include <cuda_bf16.h>

// Problem constants
#define BATCH 16
#define CH    96
#define HH    128
#define WW    128
#define BC    (BATCH*CH)          // 1536 images
#define NF    129                 // rfft bins for width 256
#define FN    256                 // padded FFT length
#define PITCH 5                   // smem pitch for 4 interleaved FFTs (+1 pad)

// Scratch (device bss, no runtime allocation)
__device__ float2 g_Krow[CH * HH * NF];        // 12.7 MB : row-rFFT of k
__device__ float2 g_Kf  [CH * NF * FN];        // 25.4 MB : full 2D FFT of k, [c][f][row]
__device__ float2 g_Xrow[BC * HH * NF];        // 203 MB  : row-rFFT of x / truncated col-inverse

// ---------------------------------------------------------------------------
// 4 interleaved radix-2 DIT FFTs of length 256, 512 threads (j = t&3 selects
// which FFT, b = t>>2 is the butterfly index 0..127). Data must be loaded in
// bit-reversed order at sr/si[k*PITCH + j]; output is natural order.
// sign = -1 forward, +1 inverse (unnormalized).
// ---------------------------------------------------------------------------
__device__ __forceinline__ void fft256x4(float* sr, float* si, int t, float sign,
                                         const float* twr, const float* twi) {
    const int j = t & 3;
    const int b = t >> 2;
    #pragma unroll
    for (int s = 0; s < 8; s++) {
        const int half = 1 << s;
        const int pos  = b & (half - 1);
        const int i0   = ((b >> s) << (s + 1)) + pos;
        const int i1   = i0 + half;
        const int ti   = pos << (7 - s);       // index into 128-entry table
        const float wr = twr[ti];
        const float wi = sign * twi[ti];
        __syncthreads();                       // previous stage (or load) done
        const float ar = sr[i0 * PITCH + j], ai = si[i0 * PITCH + j];
        const float br = sr[i1 * PITCH + j], bi = si[i1 * PITCH + j];
        const float tr = br * wr - bi * wi;
        const float tim = br * wi + bi * wr;
        sr[i0 * PITCH + j] = ar + tr;  si[i0 * PITCH + j] = ai + tim;
        sr[i1 * PITCH + j] = ar - tr;  si[i1 * PITCH + j] = ai - tim;
    }
    __syncthreads();
}

__device__ __forceinline__ void init_tw_and_zero(float* sr, float* si,
                                                 float* twr, float* twi, int t) {
    if (t < 128) {
        float a = 6.283185307179586f * (float)t / 256.0f;
        twr[t] = cosf(a);
        twi[t] = sinf(a);
    }
    for (int i = t; i < FN * PITCH; i += 512) { sr[i] = 0.0f; si[i] = 0.0f; }
    __syncthreads();
}

__device__ __forceinline__ int brev8(int v) { return (int)(__brev((unsigned)v) >> 24); }

// ---------------------------------------------------------------------------
// Kernel A: generate k via the MLP and row-rFFT it. One block = (channel c,
// 4 consecutive rows). Writes g_Krow[c][row][f].
// ---------------------------------------------------------------------------
__global__ void __launch_bounds__(512)
krow_kernel(const float* __restrict__ W1, const float* __restrict__ b1,
            const float* __restrict__ W2, const float* __restrict__ b2) {
    __shared__ float sr[FN * PITCH], si[FN * PITCH], twr[128], twi[128];
    const int t  = threadIdx.x;
    const int c  = blockIdx.x >> 5;     // 32 row-tiles per channel
    const int r0 = (blockIdx.x & 31) * 4;
    init_tw_and_zero(sr, si, twr, twi, t);

    {   // each of the 512 threads computes one k value (4 rows x 128 cols)
        const int rl  = t >> 7;
        const int col = t & 127;
        const int r   = r0 + rl;
        const float gy = (float)r  * (1.0f / 127.0f);
        const float gx = (float)col * (1.0f / 127.0f);
        float acc = b2[c];
        #pragma unroll
        for (int h = 0; h < 16; h++) {
            float hv = gy * W1[h] + gx * W1[16 + h] + b1[h];
            hv = fmaxf(hv, 0.0f);
            acc += hv * W2[h * CH + c];
        }
        sr[brev8(col) * PITCH + rl] = acc;   // imag stays 0; cols 128..255 stay 0
    }
    fft256x4(sr, si, t, -1.0f, twr, twi);

    for (int idx = t; idx < 4 * NF; idx += 512) {
        const int rl = idx / NF, f = idx - rl * NF;
        g_Krow[(c * HH + r0 + rl) * NF + f] =
            make_float2(sr[f * PITCH + rl], si[f * PITCH + rl]);
    }
}

// ---------------------------------------------------------------------------
// Kernel B: column FFT of k. One block = (c, tile of 4 freq bins).
// Writes g_Kf[c][f][k] for k = 0..255.
// ---------------------------------------------------------------------------
__global__ void __launch_bounds__(512)
kcol_kernel() {
    __shared__ float sr[FN * PITCH], si[FN * PITCH], twr[128], twi[128];
    const int t  = threadIdx.x;
    const int c  = blockIdx.x / 33;
    const int f0 = (blockIdx.x % 33) * 4;
    init_tw_and_zero(sr, si, twr, twi, t);

    {
        const int j  = t & 3;
        const int rb = t >> 2;           // row 0..127 (rows 128..255 are zero)
        const int f  = f0 + j;
        if (f < NF) {
            float2 v = g_Krow[(c * HH + rb) * NF + f];
            const int p = brev8(rb);
            sr[p * PITCH + j] = v.x;
            si[p * PITCH + j] = v.y;
        }
    }
    fft256x4(sr, si, t, -1.0f, twr, twi);

    for (int idx = t; idx < 4 * FN; idx += 512) {
        const int jj = idx >> 8, k = idx & 255;
        const int f = f0 + jj;
        if (f < NF)
            g_Kf[(c * NF + f) * FN + k] =
                make_float2(sr[k * PITCH + jj], si[k * PITCH + jj]);
    }
}

// ---------------------------------------------------------------------------
// Kernel C: row rFFT of x. One block = (image bc, 4 rows). -> g_Xrow.
// ---------------------------------------------------------------------------
__global__ void __launch_bounds__(512)
xrow_kernel(const float* __restrict__ x) {
    __shared__ float sr[FN * PITCH], si[FN * PITCH], twr[128], twi[128];
    const int t  = threadIdx.x;
    const int bc = blockIdx.x >> 5;
    const int r0 = (blockIdx.x & 31) * 4;
    init_tw_and_zero(sr, si, twr, twi, t);

    {
        const int rl  = t >> 7;
        const int col = t & 127;
        const float v = x[(bc * HH + r0 + rl) * WW + col];
        sr[brev8(col) * PITCH + rl] = v;
    }
    fft256x4(sr, si, t, -1.0f, twr, twi);

    for (int idx = t; idx < 4 * NF; idx += 512) {
        const int rl = idx / NF, f = idx - rl * NF;
        g_Xrow[(bc * HH + r0 + rl) * NF + f] =
            make_float2(sr[f * PITCH + rl], si[f * PITCH + rl]);
    }
}

// ---------------------------------------------------------------------------
// Kernel D: fused column FFT -> multiply by Kf -> column inverse FFT,
// in place on g_Xrow, keeping only rows 0..127. One block = (bc, 4 freq bins).
// ---------------------------------------------------------------------------
__global__ void __launch_bounds__(512)
conv_kernel() {
    __shared__ float sr[FN * PITCH], si[FN * PITCH], twr[128], twi[128];
    const int t  = threadIdx.x;
    const int bc = blockIdx.x / 33;
    const int c  = bc % CH;
    const int f0 = (blockIdx.x % 33) * 4;
    init_tw_and_zero(sr, si, twr, twi, t);

    {   // load 128 rows (rest zero), bit-reversed row index
        const int j  = t & 3;
        const int rb = t >> 2;
        const int f  = f0 + j;
        if (f < NF) {
            float2 v = g_Xrow[(bc * HH + rb) * NF + f];
            const int p = brev8(rb);
            sr[p * PITCH + j] = v.x;
            si[p * PITCH + j] = v.y;
        }
    }
    fft256x4(sr, si, t, -1.0f, twr, twi);   // forward along columns

    // pointwise multiply by K̂ (natural order k)
    for (int idx = t; idx < 4 * FN; idx += 512) {
        const int jj = idx >> 8, k = idx & 255;
        const int f = f0 + jj;
        if (f < NF) {
            const float2 kv = g_Kf[(c * NF + f) * FN + k];
            const int s = k * PITCH + jj;
            const float a = sr[s], b = si[s];
            sr[s] = a * kv.x - b * kv.y;
            si[s] = a * kv.y + b * kv.x;
        }
    }
    __syncthreads();

    // in-place bit reversal before the inverse DIT pass
    for (int idx = t; idx < 4 * FN; idx += 512) {
        const int jj = idx >> 8, k = idx & 255;
        const int p = brev8(k);
        if (p > k) {
            const int s0 = k * PITCH + jj, s1 = p * PITCH + jj;
            float tr = sr[s0]; sr[s0] = sr[s1]; sr[s1] = tr;
            float ti2 = si[s0]; si[s0] = si[s1]; si[s1] = ti2;
        }
    }
    __syncthreads();
    fft256x4(sr, si, t, 1.0f, twr, twi);    // unnormalized inverse

    {   // store back only rows 0..127 (truncation)
        const int j = t & 3;
        const int r = t >> 2;
        const int f = f0 + j;
        if (f < NF)
            g_Xrow[(bc * HH + r) * NF + f] =
                make_float2(sr[r * PITCH + j], si[r * PITCH + j]);
    }
}

// ---------------------------------------------------------------------------
// Kernel E: hermitian inverse row FFT (unnormalized), truncate to 128 cols,
// add residual x, write output. One block = (bc, 4 rows).
// ---------------------------------------------------------------------------
__global__ void __launch_bounds__(512)
irow_kernel(const float* __restrict__ x, float* __restrict__ out) {
    __shared__ float sr[FN * PITCH], si[FN * PITCH], twr[128], twi[128];
    const int t  = threadIdx.x;
    const int bc = blockIdx.x >> 5;
    const int r0 = (blockIdx.x & 31) * 4;
    init_tw_and_zero(sr, si, twr, twi, t);

    for (int idx = t; idx < 4 * NF; idx += 512) {
        const int rl = idx / NF, f = idx - rl * NF;
        float2 v = g_Xrow[(bc * HH + r0 + rl) * NF + f];
        sr[brev8(f) * PITCH + rl] = v.x;
        si[brev8(f) * PITCH + rl] = v.y;
        if (f >= 1 && f <= 127) {            // hermitian extension
            const int f2 = FN - f;           // 256 - f  (mirror bin, 129..255)
            sr[brev8(f2) * PITCH + rl] = v.x;
            si[brev8(f2) * PITCH + rl] = -v.y;
        }
    }
    fft256x4(sr, si, t, 1.0f, twr, twi);     // unnormalized inverse, real output

    {
        const int rl  = t >> 7;
        const int col = t & 127;
        const int gi  = (bc * HH + r0 + rl) * WW + col;
        out[gi] = sr[col * PITCH + rl] + x[gi];
    }
}

// ---------------------------------------------------------------------------
extern "C" void kernel_launch(void* const* d_in, const int* in_sizes, int n_in,
                              void* d_out, int out_size) {
    const float* x  = (const float*)d_in[0];
    const float* W1 = (const float*)d_in[1];
    const float* b1 = (const float*)d_in[2];
    const float* W2 = (const float*)d_in[3];
    const float* b2 = (const float*)d_in[4];
    float* out = (float*)d_out;

    krow_kernel<<<CH * 32, 512>>>(W1, b1, W2, b2);
    kcol_kernel<<<CH * 33, 512>>>();
    xrow_kernel<<<BC * 32, 512>>>(x);
    conv_kernel<<<BC * 33, 512>>>();
    irow_kernel<<<BC * 32, 512>>>(x, out);
}

// round 3
// speedup vs baseline: 5.1996x; 5.1996x over previous
#include <cuda_runtime.h>
#include <cuda_bf16.h>

#define CH 96
#define HH 128
#define WW 128
#define BC 1536
#define NF 129
#define XP 144            // padded row pitch (float2) -> 16-bin slices are 128B-aligned
#define GROUPS 16
#define THREADS 256

// digit-reversed base-4 position of output bin k after in-register fft16
#define P16(k) ((((k) & 3) << 2) | ((k) >> 2))

__device__ float2 g_Krow[CH * HH * XP];      // row-rFFT of k
__device__ float2 g_Kf  [CH * NF * 256];     // full 2D FFT of k  [c][f][m]
__device__ float2 g_Xrow[BC * HH * XP];      // row-rFFT of x / truncated col-inverse

// ---------------------------------------------------------------------------
template<int SGN>
__device__ __forceinline__ void fft4(float& r0, float& i0, float& r1, float& i1,
                                     float& r2, float& i2, float& r3, float& i3) {
    float t0r = r0 + r2, t0i = i0 + i2, t1r = r0 - r2, t1i = i0 - i2;
    float t2r = r1 + r3, t2i = i1 + i3, t3r = r1 - r3, t3i = i1 - i3;
    // w3 = (SGN*i) * t3
    float w3r = (SGN < 0) ? t3i : -t3i;
    float w3i = (SGN < 0) ? -t3r : t3r;
    r0 = t0r + t2r; i0 = t0i + t2i;
    r2 = t0r - t2r; i2 = t0i - t2i;
    r1 = t1r + w3r; i1 = t1i + w3i;
    r3 = t1r - w3r; i3 = t1i - w3i;
}

// In-register 16-point DFT (four-step 4x4). Input natural order x[n] in r[n].
// Output: X[4u+v] lands at position 4v+u  (i.e. X[k] at P16(k)).
template<int SGN>
__device__ __forceinline__ void fft16(float* r, float* im) {
    #pragma unroll
    for (int b = 0; b < 4; b++)
        fft4<SGN>(r[b], im[b], r[b+4], im[b+4], r[b+8], im[b+8], r[b+12], im[b+12]);
    const float TC[10] = {1.f, 0.92387953f, 0.70710678f, 0.38268343f, 0.f,
                          0.f, -0.70710678f, 0.f, 0.f, -0.92387953f};
    const float TS[10] = {0.f, 0.38268343f, 0.70710678f, 0.92387953f, 1.f,
                          0.f, 0.70710678f, 0.f, 0.f, -0.38268343f};
    #pragma unroll
    for (int k1 = 1; k1 < 4; k1++)
        #pragma unroll
        for (int b = 1; b < 4; b++) {
            const int m = k1 * b, p = 4 * k1 + b;
            const float c = TC[m], s = (float)SGN * TS[m];
            float vr = r[p] * c - im[p] * s;
            im[p]    = r[p] * s + im[p] * c;
            r[p]     = vr;
        }
    #pragma unroll
    for (int k1 = 0; k1 < 4; k1++)
        fft4<SGN>(r[4*k1], im[4*k1], r[4*k1+1], im[4*k1+1],
                  r[4*k1+2], im[4*k1+2], r[4*k1+3], im[4*k1+3]);
}

// 256-point FFT by 16 cooperating threads (one half-warp group).
// Thread j enters holding z[16*n1 + j] in zr[n1]/zi[n1] (natural n1 order).
// Thread j exits holding X[16*k2 + j] at position P16(k2).
// sr/si: per-group 272-float smem regions (17-float row pitch, conflict-free).
template<int SGN>
__device__ __forceinline__ void fft256_grp(float* zr, float* zi,
                                           float* sr, float* si, int j) {
    fft16<SGN>(zr, zi);
    float ang = (float)SGN * (6.2831853071795864f / 256.f) * (float)j;
    float wjs, wjc;
    __sincosf(ang, &wjs, &wjc);          // Wj = e^{SGN*2*pi*i*j/256}
    float wr = 1.f, wi = 0.f;
    __syncwarp();                        // prior reads of this region are done
    #pragma unroll
    for (int k1 = 0; k1 < 16; k1++) {
        const int p = P16(k1);
        sr[k1 * 17 + j] = zr[p] * wr - zi[p] * wi;
        si[k1 * 17 + j] = zr[p] * wi + zi[p] * wr;
        float nr = wr * wjc - wi * wjs;
        wi = wr * wjs + wi * wjc; wr = nr;
    }
    __syncwarp();
    #pragma unroll
    for (int n2 = 0; n2 < 16; n2++) { zr[n2] = sr[j*17 + n2]; zi[n2] = si[j*17 + n2]; }
    fft16<SGN>(zr, zi);
}

// ---------------------------------------------------------------------------
// Kernel A: MLP -> k values -> row rFFT.  grid = CH*8, 16 rows per block.
__global__ void __launch_bounds__(THREADS)
krow_kernel(const float* __restrict__ W1, const float* __restrict__ b1,
            const float* __restrict__ W2, const float* __restrict__ b2) {
    __shared__ float s_r[GROUPS*272], s_i[GROUPS*272];
    const int t = threadIdx.x, g = t >> 4, j = t & 15;
    const int c = blockIdx.x >> 3;
    const int r = ((blockIdx.x & 7) << 4) + g;
    float w1a[16], w1b[16], bb1[16], w2[16];
    #pragma unroll
    for (int h = 0; h < 16; h++) {
        w1a[h] = W1[h]; w1b[h] = W1[16 + h]; bb1[h] = b1[h]; w2[h] = W2[h * CH + c];
    }
    const float bias = b2[c];
    const float gy = (float)r * (1.f / 127.f);
    float zr[16], zi[16];
    #pragma unroll
    for (int n1 = 0; n1 < 16; n1++) {
        const int col = n1 * 16 + j;
        float v = 0.f;
        if (col < 128) {
            const float gx = (float)col * (1.f / 127.f);
            float acc = bias;
            #pragma unroll
            for (int h = 0; h < 16; h++)
                acc += fmaxf(gy * w1a[h] + gx * w1b[h] + bb1[h], 0.f) * w2[h];
            v = acc;
        }
        zr[n1] = v; zi[n1] = 0.f;
    }
    fft256_grp<-1>(zr, zi, s_r + g*272, s_i + g*272, j);
    const int base = (c * HH + r) * XP;
    #pragma unroll
    for (int k2 = 0; k2 < 8; k2++)
        g_Krow[base + k2*16 + j] = make_float2(zr[P16(k2)], zi[P16(k2)]);
    if (j == 0)
        g_Krow[base + 128] = make_float2(zr[P16(8)], zi[P16(8)]);
}

// Kernel B: column FFT of k.  grid = CH*9, 16 bins per block (idle pad groups).
__global__ void __launch_bounds__(THREADS)
kcol_kernel() {
    __shared__ float s_r[GROUPS*272], s_i[GROUPS*272];
    const int t = threadIdx.x, g = t >> 4, j = t & 15;
    const int c = blockIdx.x / 9;
    const int f = (blockIdx.x % 9) * 16 + g;
    const bool act = (f <= 128);
    float zr[16], zi[16];
    #pragma unroll
    for (int n1 = 0; n1 < 16; n1++) {
        const int row = n1 * 16 + j;
        float2 v = make_float2(0.f, 0.f);
        if (act && row < 128) v = g_Krow[(c * HH + row) * XP + f];
        zr[n1] = v.x; zi[n1] = v.y;
    }
    fft256_grp<-1>(zr, zi, s_r + g*272, s_i + g*272, j);
    if (act) {
        const int base = (c * NF + f) * 256;
        #pragma unroll
        for (int k2 = 0; k2 < 16; k2++)
            g_Kf[base + k2*16 + j] = make_float2(zr[P16(k2)], zi[P16(k2)]);
    }
}

// Kernel C: row rFFT of x.  grid = BC*8.
__global__ void __launch_bounds__(THREADS)
xrow_kernel(const float* __restrict__ x) {
    __shared__ float s_r[GROUPS*272], s_i[GROUPS*272];
    const int t = threadIdx.x, g = t >> 4, j = t & 15;
    const int bc = blockIdx.x >> 3;
    const int r  = ((blockIdx.x & 7) << 4) + g;
    const int xb = (bc * HH + r) * WW;
    float zr[16], zi[16];
    #pragma unroll
    for (int n1 = 0; n1 < 16; n1++) {
        const int col = n1 * 16 + j;
        zr[n1] = (col < 128) ? x[xb + col] : 0.f;
        zi[n1] = 0.f;
    }
    fft256_grp<-1>(zr, zi, s_r + g*272, s_i + g*272, j);
    const int base = (bc * HH + r) * XP;
    #pragma unroll
    for (int k2 = 0; k2 < 8; k2++)
        g_Xrow[base + k2*16 + j] = make_float2(zr[P16(k2)], zi[P16(k2)]);
    if (j == 0)
        g_Xrow[base + 128] = make_float2(zr[P16(8)], zi[P16(8)]);
}

// Kernel D: col FFT * Kf * col iFFT, in place, keep rows 0..127. grid = BC*9.
__global__ void __launch_bounds__(THREADS)
conv_kernel() {
    __shared__ float s_r[GROUPS*272], s_i[GROUPS*272];
    const int t = threadIdx.x, g = t >> 4, j = t & 15;
    const int bc = blockIdx.x / 9;
    const int c  = bc % CH;
    const int f  = (blockIdx.x % 9) * 16 + g;
    const bool act = (f <= 128);
    float zr[16], zi[16];
    #pragma unroll
    for (int n1 = 0; n1 < 16; n1++) {
        const int row = n1 * 16 + j;
        float2 v = make_float2(0.f, 0.f);
        if (act && row < 128) v = g_Xrow[(bc * HH + row) * XP + f];
        zr[n1] = v.x; zi[n1] = v.y;
    }
    fft256_grp<-1>(zr, zi, s_r + g*272, s_i + g*272, j);   // forward along columns
    if (act) {
        const int kb = (c * NF + f) * 256;
        #pragma unroll
        for (int k2 = 0; k2 < 16; k2++) {
            const float2 kv = g_Kf[kb + k2*16 + j];
            const int p = P16(k2);
            const float a = zr[p], b = zi[p];
            zr[p] = a * kv.x - b * kv.y;
            zi[p] = a * kv.y + b * kv.x;
        }
    }
    // product for m = 16*m1 + j sits at P16(m1); un-permute to natural order
    float yr[16], yi[16];
    #pragma unroll
    for (int n1 = 0; n1 < 16; n1++) { yr[n1] = zr[P16(n1)]; yi[n1] = zi[P16(n1)]; }
    fft256_grp<1>(yr, yi, s_r + g*272, s_i + g*272, j);    // unnormalized inverse
    if (act) {
        #pragma unroll
        for (int k2 = 0; k2 < 8; k2++)
            g_Xrow[(bc * HH + k2*16 + j) * XP + f] =
                make_float2(yr[P16(k2)], yi[P16(k2)]);
    }
}

// Kernel E: hermitian inverse row FFT + residual add.  grid = BC*8.
__global__ void __launch_bounds__(THREADS)
irow_kernel(const float* __restrict__ x, float* __restrict__ out) {
    __shared__ float s_r[GROUPS*272], s_i[GROUPS*272];
    const int t = threadIdx.x, g = t >> 4, j = t & 15;
    const int bc = blockIdx.x >> 3;
    const int r  = ((blockIdx.x & 7) << 4) + g;
    const int base = (bc * HH + r) * XP;
    float zr[16], zi[16];
    #pragma unroll
    for (int n1 = 0; n1 < 16; n1++) {
        const int n = n1 * 16 + j;
        if (n <= 128) {
            const float2 v = g_Xrow[base + n];
            zr[n1] = v.x; zi[n1] = v.y;
        } else {
            const float2 v = g_Xrow[base + 256 - n];   // hermitian mirror
            zr[n1] = v.x; zi[n1] = -v.y;
        }
    }
    fft256_grp<1>(zr, zi, s_r + g*272, s_i + g*272, j);    // unnormalized inverse
    const int gi = (bc * HH + r) * WW;
    #pragma unroll
    for (int k2 = 0; k2 < 8; k2++) {
        const int col = k2 * 16 + j;
        out[gi + col] = zr[P16(k2)] + x[gi + col];
    }
}

// ---------------------------------------------------------------------------
extern "C" void kernel_launch(void* const* d_in, const int* in_sizes, int n_in,
                              void* d_out, int out_size) {
    const float* x  = (const float*)d_in[0];
    const float* W1 = (const float*)d_in[1];
    const float* b1 = (const float*)d_in[2];
    const float* W2 = (const float*)d_in[3];
    const float* b2 = (const float*)d_in[4];
    float* out = (float*)d_out;

    krow_kernel<<<CH * 8, THREADS>>>(W1, b1, W2, b2);
    kcol_kernel<<<CH * 9, THREADS>>>();
    xrow_kernel<<<BC * 8, THREADS>>>(x);
    conv_kernel<<<BC * 9, THREADS>>>();
    irow_kernel<<<BC * 8, THREADS>>>(x, out);
}

// round 5
// speedup vs baseline: 6.6041x; 1.2701x over previous
#include <cuda_runtime.h>
#include <cuda_bf16.h>

#define CH 96
#define HH 128
#define WW 128
#define BC 1536
#define NF 129
#define XP 144            // pitch for g_Krow
#define THREADS 512       // 32 groups of 16 threads

// digit-reversed base-4 position of output bin k after in-register fft16
#define P16(k) ((((k) & 3) << 2) | ((k) >> 2))

__device__ float2 g_Krow[CH * HH * XP];      // row-rFFT of k
__device__ float2 g_Kf  [CH * NF * 256];     // full 2D FFT of k  [c][f][m]

// smem partition (floats): tile_r[16512] tile_i[16512] scr_r[8704] scr_i[8704]
#define TILE_N   16512                       // 128 rows * 129 bins
#define SCR_N    8704                        // 32 groups * 272
#define SMEM_FLOATS (2*TILE_N + 2*SCR_N)     // 50432 -> 201728 bytes
#define TP 129                               // tile pitch (odd -> col access conflict-free)

// ---------------------------------------------------------------------------
template<int SGN>
__device__ __forceinline__ void fft4(float& r0, float& i0, float& r1, float& i1,
                                     float& r2, float& i2, float& r3, float& i3) {
    float t0r = r0 + r2, t0i = i0 + i2, t1r = r0 - r2, t1i = i0 - i2;
    float t2r = r1 + r3, t2i = i1 + i3, t3r = r1 - r3, t3i = i1 - i3;
    float w3r = (SGN < 0) ? t3i : -t3i;
    float w3i = (SGN < 0) ? -t3r : t3r;
    r0 = t0r + t2r; i0 = t0i + t2i;
    r2 = t0r - t2r; i2 = t0i - t2i;
    r1 = t1r + w3r; i1 = t1i + w3i;
    r3 = t1r - w3r; i3 = t1i - w3i;
}

template<int SGN>
__device__ __forceinline__ void fft16(float* r, float* im) {
    #pragma unroll
    for (int b = 0; b < 4; b++)
        fft4<SGN>(r[b], im[b], r[b+4], im[b+4], r[b+8], im[b+8], r[b+12], im[b+12]);
    const float TC[10] = {1.f, 0.92387953f, 0.70710678f, 0.38268343f, 0.f,
                          0.f, -0.70710678f, 0.f, 0.f, -0.92387953f};
    const float TS[10] = {0.f, 0.38268343f, 0.70710678f, 0.92387953f, 1.f,
                          0.f, 0.70710678f, 0.f, 0.f, -0.38268343f};
    #pragma unroll
    for (int k1 = 1; k1 < 4; k1++)
        #pragma unroll
        for (int b = 1; b < 4; b++) {
            const int m = k1 * b, p = 4 * k1 + b;
            const float c = TC[m], s = (float)SGN * TS[m];
            float vr = r[p] * c - im[p] * s;
            im[p]    = r[p] * s + im[p] * c;
            r[p]     = vr;
        }
    #pragma unroll
    for (int k1 = 0; k1 < 4; k1++)
        fft4<SGN>(r[4*k1], im[4*k1], r[4*k1+1], im[4*k1+1],
                  r[4*k1+2], im[4*k1+2], r[4*k1+3], im[4*k1+3]);
}

// 256-pt FFT by one 16-thread group; thread j enters with z[16*n1+j] natural,
// exits with X[16*k2+j] at position P16(k2). sr/si: per-group 272-float scratch.
template<int SGN>
__device__ __forceinline__ void fft256_grp(float* zr, float* zi,
                                           float* sr, float* si, int j) {
    fft16<SGN>(zr, zi);
    float ang = (float)SGN * (6.2831853071795864f / 256.f) * (float)j;
    float wjs, wjc;
    __sincosf(ang, &wjs, &wjc);
    float wr = 1.f, wi = 0.f;
    __syncwarp();
    #pragma unroll
    for (int k1 = 0; k1 < 16; k1++) {
        const int p = P16(k1);
        sr[k1 * 17 + j] = zr[p] * wr - zi[p] * wi;
        si[k1 * 17 + j] = zr[p] * wi + zi[p] * wr;
        float nr = wr * wjc - wi * wjs;
        wi = wr * wjs + wi * wjc; wr = nr;
    }
    __syncwarp();
    #pragma unroll
    for (int n2 = 0; n2 < 16; n2++) { zr[n2] = sr[j*17 + n2]; zi[n2] = si[j*17 + n2]; }
    fft16<SGN>(zr, zi);
}

// ---------------------------------------------------------------------------
// Kernel A: MLP -> k values -> row rFFT.  grid = CH*8, 16 rows per block.
__global__ void __launch_bounds__(256)
krow_kernel(const float* __restrict__ W1, const float* __restrict__ b1,
            const float* __restrict__ W2, const float* __restrict__ b2) {
    __shared__ float s_r[16*272], s_i[16*272];
    const int t = threadIdx.x, g = t >> 4, j = t & 15;
    const int c = blockIdx.x >> 3;
    const int r = ((blockIdx.x & 7) << 4) + g;
    float w1a[16], w1b[16], bb1[16], w2[16];
    #pragma unroll
    for (int h = 0; h < 16; h++) {
        w1a[h] = W1[h]; w1b[h] = W1[16 + h]; bb1[h] = b1[h]; w2[h] = W2[h * CH + c];
    }
    const float bias = b2[c];
    const float gy = (float)r * (1.f / 127.f);
    float zr[16], zi[16];
    #pragma unroll
    for (int n1 = 0; n1 < 16; n1++) {
        const int col = n1 * 16 + j;
        float v = 0.f;
        if (col < 128) {
            const float gx = (float)col * (1.f / 127.f);
            float acc = bias;
            #pragma unroll
            for (int h = 0; h < 16; h++)
                acc += fmaxf(gy * w1a[h] + gx * w1b[h] + bb1[h], 0.f) * w2[h];
            v = acc;
        }
        zr[n1] = v; zi[n1] = 0.f;
    }
    fft256_grp<-1>(zr, zi, s_r + g*272, s_i + g*272, j);
    const int base = (c * HH + r) * XP;
    #pragma unroll
    for (int k2 = 0; k2 < 8; k2++)
        g_Krow[base + k2*16 + j] = make_float2(zr[P16(k2)], zi[P16(k2)]);
    if (j == 0)
        g_Krow[base + 128] = make_float2(zr[P16(8)], zi[P16(8)]);
}

// Kernel B: column FFT of k.  grid = CH*9.
__global__ void __launch_bounds__(256)
kcol_kernel() {
    __shared__ float s_r[16*272], s_i[16*272];
    const int t = threadIdx.x, g = t >> 4, j = t & 15;
    const int c = blockIdx.x / 9;
    const int f = (blockIdx.x % 9) * 16 + g;
    const bool act = (f <= 128);
    float zr[16], zi[16];
    #pragma unroll
    for (int n1 = 0; n1 < 16; n1++) {
        const int row = n1 * 16 + j;
        float2 v = make_float2(0.f, 0.f);
        if (act && row < 128) v = g_Krow[(c * HH + row) * XP + f];
        zr[n1] = v.x; zi[n1] = v.y;
    }
    fft256_grp<-1>(zr, zi, s_r + g*272, s_i + g*272, j);
    if (act) {
        const int base = (c * NF + f) * 256;
        #pragma unroll
        for (int k2 = 0; k2 < 16; k2++)
            g_Kf[base + k2*16 + j] = make_float2(zr[P16(k2)], zi[P16(k2)]);
    }
}

// ---------------------------------------------------------------------------
// Fused per-image kernel: row rFFT -> (col FFT * Kf * col iFFT) -> row iFFT
// + residual. One block = one image. 32 groups of 16 threads.
// ---------------------------------------------------------------------------
__global__ void __launch_bounds__(THREADS)
fused_kernel(const float* __restrict__ x, float* __restrict__ out) {
    extern __shared__ float smem[];
    float* tr = smem;
    float* ti = smem + TILE_N;
    float* fr = smem + 2*TILE_N;
    float* fi = smem + 2*TILE_N + SCR_N;

    const int t = threadIdx.x, g = t >> 4, j = t & 15;
    const int bc = blockIdx.x;
    const int c  = bc % CH;
    float* sr = fr + g*272;
    float* si = fi + g*272;

    // ---- Phase 1: row rFFTs of x (128 rows, 32 groups, 4 iters) ----
    #pragma unroll 1
    for (int it = 0; it < 4; it++) {
        const int r  = it * 32 + g;
        const int xb = (bc * HH + r) * WW;
        float zr[16], zi[16];
        #pragma unroll
        for (int n1 = 0; n1 < 16; n1++) {
            const int col = n1 * 16 + j;
            zr[n1] = (col < 128) ? x[xb + col] : 0.f;
            zi[n1] = 0.f;
        }
        fft256_grp<-1>(zr, zi, sr, si, j);
        const int base = r * TP;
        #pragma unroll
        for (int k2 = 0; k2 < 8; k2++) {
            tr[base + k2*16 + j] = zr[P16(k2)];
            ti[base + k2*16 + j] = zi[P16(k2)];
        }
        if (j == 0) { tr[base + 128] = zr[P16(8)]; ti[base + 128] = zi[P16(8)]; }
    }
    __syncthreads();

    // ---- Phase 2: per-column fwd FFT * Kf * inv FFT (129 cols, 5 iters) ----
    #pragma unroll 1
    for (int it = 0; it < 5; it++) {
        const int f = it * 32 + g;
        const bool act = (f <= 128);
        float zr[16], zi[16];
        #pragma unroll
        for (int n1 = 0; n1 < 16; n1++) {
            const int row = n1 * 16 + j;          // rows >=128 are zero pad
            if (act && row < 128) {
                zr[n1] = tr[row * TP + f];
                zi[n1] = ti[row * TP + f];
            } else { zr[n1] = 0.f; zi[n1] = 0.f; }
        }
        fft256_grp<-1>(zr, zi, sr, si, j);        // forward along column
        if (act) {
            const int kb = (c * NF + f) * 256;
            #pragma unroll
            for (int k2 = 0; k2 < 16; k2++) {
                const float2 kv = g_Kf[kb + k2*16 + j];
                const int p = P16(k2);
                const float a = zr[p], b = zi[p];
                zr[p] = a * kv.x - b * kv.y;
                zi[p] = a * kv.y + b * kv.x;
            }
        }
        float yr[16], yi[16];
        #pragma unroll
        for (int n1 = 0; n1 < 16; n1++) { yr[n1] = zr[P16(n1)]; yi[n1] = zi[P16(n1)]; }
        fft256_grp<1>(yr, yi, sr, si, j);         // unnormalized inverse
        if (act) {
            #pragma unroll
            for (int k2 = 0; k2 < 8; k2++) {      // keep only rows 0..127
                const int row = k2 * 16 + j;
                tr[row * TP + f] = yr[P16(k2)];
                ti[row * TP + f] = yi[P16(k2)];
            }
        }
    }
    __syncthreads();

    // ---- Phase 3: hermitian inverse row FFT + residual (128 rows, 4 iters) ----
    #pragma unroll 1
    for (int it = 0; it < 4; it++) {
        const int r    = it * 32 + g;
        const int base = r * TP;
        float zr[16], zi[16];
        #pragma unroll
        for (int n1 = 0; n1 < 16; n1++) {
            const int n = n1 * 16 + j;
            if (n <= 128) {
                zr[n1] = tr[base + n];
                zi[n1] = ti[base + n];
            } else {                               // hermitian mirror: conj(bin 256-n)
                zr[n1] = tr[base + 256 - n];
                zi[n1] = -ti[base + 256 - n];
            }
        }
        fft256_grp<1>(zr, zi, sr, si, j);          // unnormalized inverse, real out
        const int gi = (bc * HH + r) * WW;
        #pragma unroll
        for (int k2 = 0; k2 < 8; k2++) {
            const int col = k2 * 16 + j;
            out[gi + col] = zr[P16(k2)] + x[gi + col];
        }
    }
}

// ---------------------------------------------------------------------------
extern "C" void kernel_launch(void* const* d_in, const int* in_sizes, int n_in,
                              void* d_out, int out_size) {
    const float* x  = (const float*)d_in[0];
    const float* W1 = (const float*)d_in[1];
    const float* b1 = (const float*)d_in[2];
    const float* W2 = (const float*)d_in[3];
    const float* b2 = (const float*)d_in[4];
    float* out = (float*)d_out;

    static int smem_set = 0;
    if (!smem_set) {
        cudaFuncSetAttribute(fused_kernel,
                             cudaFuncAttributeMaxDynamicSharedMemorySize,
                             SMEM_FLOATS * (int)sizeof(float));
        smem_set = 1;
    }

    krow_kernel<<<CH * 8, 256>>>(W1, b1, W2, b2);
    kcol_kernel<<<CH * 9, 256>>>();
    fused_kernel<<<BC, THREADS, SMEM_FLOATS * sizeof(float)>>>(x, out);
}